// round 12
// baseline (speedup 1.0000x reference)
#include <cuda_runtime.h>
#include <cstdint>

#define N_NODES 100000
#define N_EDGES 3200000
#define IN_F    1433
#define HID     16
#define OUTF    7
#define OUTP    8

#define G1_THREADS 512
#define G1_ROWS    676   // 148 * 676 = 100048 >= N_NODES
#define G1_GRID    148
#define CW16       16    // k-chunk width
#define PAD16      20    // smem row stride (floats): 80B, 16B-aligned, conflict-free
#define NCHUNK16   90    // ceil(1433/16); last chunk = 9 cols
#define CP_ITERS   22    // ceil(676*16/512)

#define SW_FLOATS  (IN_F * HID)          // 22928
#define SF_FLOATS  (G1_ROWS * PAD16)     // 13520
#define SMEM_TOTAL ((SW_FLOATS + 2 * SF_FLOATS) * 4)   // 199872 B

#define SCAN_BLK  1024
#define SCAN_NBLK 98     // 98*1024 = 100352 >= N_NODES

// ---------------- scratch (static device globals; no allocation) ------------
__device__ __align__(16) float g_norm_src[N_NODES];
__device__ __align__(16) float g_norm_dst[N_NODES];
__device__ __align__(16) int   g_deg_out[N_NODES];
__device__ __align__(16) int   g_deg_in [N_NODES];
__device__ __align__(16) int   g_intra  [N_NODES];      // intra-block excl scan
__device__ int   g_bsum[SCAN_NBLK];
__device__ int   g_boff[SCAN_NBLK];
__device__ __align__(16) int   g_off   [N_NODES + 1];   // CSR row offsets (by dst)
__device__ __align__(16) int   g_cursor[N_NODES];
__device__ __align__(16) int   g_csr_src[N_EDGES];      // src ids grouped by dst
__device__ __align__(16) float g_x1[N_NODES * HID];     // (X*ns)@W1
__device__ __align__(16) float g_x2[N_NODES * OUTP];    // (h*ns)@W2, padded
__device__ int g_is64;

// ---------------- small PTX helpers ----------------------------------------
__device__ __forceinline__ unsigned long long pk2(float lo, float hi) {
    unsigned long long r;
    asm("mov.b64 %0, {%1, %2};" : "=l"(r) : "f"(lo), "f"(hi));
    return r;
}
__device__ __forceinline__ float2 upk2(unsigned long long v) {
    float2 f;
    asm("mov.b64 {%0, %1}, %2;" : "=f"(f.x), "=f"(f.y) : "l"(v));
    return f;
}
__device__ __forceinline__ void fma2(unsigned long long& a,
                                     unsigned long long x,
                                     unsigned long long w) {
    asm("fma.rn.f32x2 %0, %1, %2, %0;" : "+l"(a) : "l"(x), "l"(w));
}
__device__ __forceinline__ void cp4(uint32_t dst, const float* src) {
    asm volatile("cp.async.ca.shared.global [%0], [%1], 4;"
                 :: "r"(dst), "l"(src));
}
#define CP_COMMIT() asm volatile("cp.async.commit_group;" ::: "memory")
#define CP_WAIT1()  asm volatile("cp.async.wait_group 1;" ::: "memory")

// ---------------- setup -----------------------------------------------------
__global__ void zero_detect_kernel(const unsigned long long* __restrict__ ei) {
    int i = blockIdx.x * blockDim.x + threadIdx.x;
    if (i < N_NODES) { g_deg_out[i] = 0; g_deg_in[i] = 0; }
    if (i == 0) {
        unsigned long long mx = 0;
#pragma unroll
        for (int j = 0; j < 16; j++) mx = mx < ei[j] ? ei[j] : mx;
        g_is64 = (mx < (1ull << 32)) ? 1 : 0;
    }
}

__device__ __forceinline__ void load_edge(const long long* ei, int e,
                                          int& s, int& d) {
    if (g_is64) {
        s = (int)ei[e];
        d = (int)ei[N_EDGES + e];
    } else {
        const int* e32 = reinterpret_cast<const int*>(ei);
        s = e32[e];
        d = e32[N_EDGES + e];
    }
}

__global__ void degree_kernel(const long long* __restrict__ ei) {
    int e = blockIdx.x * blockDim.x + threadIdx.x;
    if (e >= N_EDGES) return;
    int s, d;
    load_edge(ei, e, s, d);
    atomicAdd(g_deg_out + s, 1);
    atomicAdd(g_deg_in + d, 1);
}

// scan over deg_in (block-level) + fused norm computation
__global__ void scan1_kernel() {
    __shared__ int tmp[SCAN_BLK];
    int t = threadIdx.x;
    int i = blockIdx.x * SCAN_BLK + t;
    int v = (i < N_NODES) ? g_deg_in[i] : 0;
    if (i < N_NODES) {
        g_norm_src[i] = rsqrtf(fmaxf((float)g_deg_out[i], 1.f));
        g_norm_dst[i] = rsqrtf(fmaxf((float)v, 1.f));
    }
    tmp[t] = v;
    __syncthreads();
#pragma unroll
    for (int off = 1; off < SCAN_BLK; off <<= 1) {
        int a = (t >= off) ? tmp[t - off] : 0;
        __syncthreads();
        tmp[t] += a;
        __syncthreads();
    }
    if (i < N_NODES) g_intra[i] = tmp[t] - v;   // exclusive
    if (t == SCAN_BLK - 1) g_bsum[blockIdx.x] = tmp[t];
}

__global__ void scan2_kernel() {
    __shared__ int tmp[128];
    int t = threadIdx.x;
    int v = (t < SCAN_NBLK) ? g_bsum[t] : 0;
    tmp[t] = v;
    __syncthreads();
#pragma unroll
    for (int off = 1; off < 128; off <<= 1) {
        int a = (t >= off) ? tmp[t - off] : 0;
        __syncthreads();
        tmp[t] += a;
        __syncthreads();
    }
    if (t < SCAN_NBLK) g_boff[t] = tmp[t] - v;  // exclusive
    if (t == 127) g_off[N_NODES] = tmp[127];    // == N_EDGES
}

__global__ void scan3_kernel() {
    int i = blockIdx.x * blockDim.x + threadIdx.x;
    if (i >= N_NODES) return;
    int v = g_boff[i >> 10] + g_intra[i];
    g_off[i] = v;
    g_cursor[i] = v;
}

__global__ void fill_kernel(const long long* __restrict__ ei) {
    int e = blockIdx.x * blockDim.x + threadIdx.x;
    if (e >= N_EDGES) return;
    int s, d;
    load_edge(ei, e, s, d);
    int pos = atomicAdd(g_cursor + d, 1);
    g_csr_src[pos] = s;
}

// -------- gemm1: x1[r][0:16] = norm_src[r] * (feat[r,:] @ W1) ---------------
// 148 CTAs (1/SM), 512 threads, 2 rows/thread. W1 resident in smem.
// Feature k-chunks (16 cols) stream global->shared via cp.async with two
// smem buffers; no register staging (regs stay well under the 128 cap).

__device__ __forceinline__ void body2(float x0, float x1v,
                                      const ulonglong2* __restrict__ wk,
                                      unsigned long long* a0,
                                      unsigned long long* a1) {
    unsigned long long p0 = pk2(x0, x0);
    unsigned long long p1 = pk2(x1v, x1v);
#pragma unroll
    for (int q = 0; q < 4; q++) {
        ulonglong2 u = wk[q];
        fma2(a0[2 * q],     p0, u.x);
        fma2(a0[2 * q + 1], p0, u.y);
        fma2(a1[2 * q],     p1, u.x);
        fma2(a1[2 * q + 1], p1, u.y);
    }
}
__device__ __forceinline__ void body1(float x0,
                                      const ulonglong2* __restrict__ wk,
                                      unsigned long long* a0) {
    unsigned long long p0 = pk2(x0, x0);
#pragma unroll
    for (int q = 0; q < 4; q++) {
        ulonglong2 u = wk[q];
        fma2(a0[2 * q],     p0, u.x);
        fma2(a0[2 * q + 1], p0, u.y);
    }
}

__device__ __forceinline__ void store_row(int r, unsigned long long* a) {
    float ns = g_norm_src[r];
    float4* o = reinterpret_cast<float4*>(g_x1 + (long long)r * HID);
#pragma unroll
    for (int jj = 0; jj < 4; jj++) {
        float2 e0 = upk2(a[2 * jj]), e1 = upk2(a[2 * jj + 1]);
        o[jj] = make_float4(e0.x * ns, e0.y * ns, e1.x * ns, e1.y * ns);
    }
}

__device__ __forceinline__ void issue_chunk(uint32_t sFu, const float* fb,
                                            int c, int tid, int total16) {
    const int K0 = c * CW16;
    const int CW = min(CW16, IN_F - K0);
#pragma unroll
    for (int u = 0; u < CP_ITERS; u++) {
        int f = tid + u * G1_THREADS;
        int row = f >> 4, kk = f & 15;
        if (f < total16 && kk < CW)
            cp4(sFu + (uint32_t)(row * PAD16 + kk) * 4,
                fb + (long long)row * IN_F + K0 + kk);
    }
}

__global__ void __launch_bounds__(G1_THREADS, 1)
gemm1_kernel(const float* __restrict__ feat, const float* __restrict__ W1) {
    extern __shared__ float smem[];
    float* sW = smem;                              // 22928 floats
    float* sF0 = smem + SW_FLOATS;                 // 13520 floats
    float* sF1 = smem + SW_FLOATS + SF_FLOATS;     // 13520 floats
    uint32_t sbase = (uint32_t)__cvta_generic_to_shared(smem);
    const uint32_t sFu0 = sbase + SW_FLOATS * 4;
    const uint32_t sFu1 = sbase + (SW_FLOATS + SF_FLOATS) * 4;

    const int tid   = threadIdx.x;
    const int base  = blockIdx.x * G1_ROWS;
    const int nrows = min(G1_ROWS, N_NODES - base);
    const int total16 = nrows * 16;
    const bool v1 = (G1_THREADS + tid) < nrows;    // row0 always valid
    const float* fb = feat + (long long)base * IN_F;

    // prologue: start streaming chunks 0 and 1, then load W1
    issue_chunk(sFu0, fb, 0, tid, total16);
    CP_COMMIT();
    issue_chunk(sFu1, fb, 1, tid, total16);
    CP_COMMIT();

    for (int i = tid; i < SW_FLOATS / 4; i += G1_THREADS)
        reinterpret_cast<float4*>(sW)[i] =
            reinterpret_cast<const float4*>(W1)[i];

    unsigned long long a0[8], a1[8];
#pragma unroll
    for (int j = 0; j < 8; j++) { a0[j] = 0ull; a1[j] = 0ull; }

    for (int c = 0; c < NCHUNK16; c++) {
        CP_WAIT1();           // chunk c landed (chunk c+1 may be in flight)
        __syncthreads();      // visible to all threads (also covers sW STS)

        const float* sFb = (c & 1) ? sF1 : sF0;
        const float* f0 = sFb + tid * PAD16;
        const float* f1 = sFb + (G1_THREADS + tid) * PAD16;
        const float* sWk = sW + c * CW16 * HID;

        if (c < NCHUNK16 - 1) {   // full 16-col chunk
            const float4* F0 = reinterpret_cast<const float4*>(f0);
            const float4* F1 = reinterpret_cast<const float4*>(f1);
            if (v1) {
#pragma unroll
                for (int q = 0; q < 4; q++) {
                    float4 x0 = F0[q], x1 = F1[q];
                    const float* wq = sWk + 4 * q * HID;
                    body2(x0.x, x1.x, (const ulonglong2*)(wq + 0 * HID), a0, a1);
                    body2(x0.y, x1.y, (const ulonglong2*)(wq + 1 * HID), a0, a1);
                    body2(x0.z, x1.z, (const ulonglong2*)(wq + 2 * HID), a0, a1);
                    body2(x0.w, x1.w, (const ulonglong2*)(wq + 3 * HID), a0, a1);
                }
            } else {
#pragma unroll
                for (int q = 0; q < 4; q++) {
                    float4 x0 = F0[q];
                    const float* wq = sWk + 4 * q * HID;
                    body1(x0.x, (const ulonglong2*)(wq + 0 * HID), a0);
                    body1(x0.y, (const ulonglong2*)(wq + 1 * HID), a0);
                    body1(x0.z, (const ulonglong2*)(wq + 2 * HID), a0);
                    body1(x0.w, (const ulonglong2*)(wq + 3 * HID), a0);
                }
            }
        } else {                  // tail chunk: 1433 - 89*16 = 9 cols
            const int CW = IN_F - c * CW16;
            if (v1) {
                for (int kk = 0; kk < CW; kk++)
                    body2(f0[kk], f1[kk],
                          (const ulonglong2*)(sWk + kk * HID), a0, a1);
            } else {
                for (int kk = 0; kk < CW; kk++)
                    body1(f0[kk],
                          (const ulonglong2*)(sWk + kk * HID), a0);
            }
        }
        __syncthreads();          // all threads done reading buf (c&1)

        if (c + 2 < NCHUNK16)
            issue_chunk((c & 1) ? sFu1 : sFu0, fb, c + 2, tid, total16);
        CP_COMMIT();              // commit every iter (empty group is fine)
    }

    store_row(base + tid, a0);
    if (v1) store_row(base + G1_THREADS + tid, a1);
}

// -------- gather1 (+ fused relu/bias/W2): per-dst gather-sum of x1 ----------
__global__ void gather1_kernel(const float* __restrict__ b1,
                               const float* __restrict__ W2) {
    __shared__ float sW2[HID * OUTF];
    __shared__ float sb1[HID];
    if (threadIdx.x < HID * OUTF) sW2[threadIdx.x] = W2[threadIdx.x];
    if (threadIdx.x < HID) sb1[threadIdx.x] = b1[threadIdx.x];
    __syncthreads();

    int i = blockIdx.x * blockDim.x + threadIdx.x;
    if (i >= N_NODES) return;
    int p0 = g_off[i], p1 = g_off[i + 1];

    float4 A = make_float4(0.f, 0.f, 0.f, 0.f), B = A, C = A, D = A;
    for (int p = p0; p < p1; p++) {
        int s = g_csr_src[p];
        const float4* xs =
            reinterpret_cast<const float4*>(g_x1 + (long long)s * HID);
        float4 t0 = __ldg(xs + 0), t1 = __ldg(xs + 1);
        float4 t2 = __ldg(xs + 2), t3 = __ldg(xs + 3);
        A.x += t0.x; A.y += t0.y; A.z += t0.z; A.w += t0.w;
        B.x += t1.x; B.y += t1.y; B.z += t1.z; B.w += t1.w;
        C.x += t2.x; C.y += t2.y; C.z += t2.z; C.w += t2.w;
        D.x += t3.x; D.y += t3.y; D.z += t3.z; D.w += t3.w;
    }

    float nd = g_norm_dst[i], ns = g_norm_src[i];
    float h[HID];
    float acc[HID] = { A.x, A.y, A.z, A.w, B.x, B.y, B.z, B.w,
                       C.x, C.y, C.z, C.w, D.x, D.y, D.z, D.w };
#pragma unroll
    for (int k = 0; k < HID; k++)
        h[k] = fmaxf(acc[k] * nd + sb1[k], 0.f) * ns;

    float o[OUTF];
#pragma unroll
    for (int j = 0; j < OUTF; j++) o[j] = 0.f;
#pragma unroll
    for (int k = 0; k < HID; k++) {
        float hv = h[k];
#pragma unroll
        for (int j = 0; j < OUTF; j++) o[j] += hv * sW2[k * OUTF + j];
    }
    float4* xo = reinterpret_cast<float4*>(g_x2 + (long long)i * OUTP);
    xo[0] = make_float4(o[0], o[1], o[2], o[3]);
    xo[1] = make_float4(o[4], o[5], o[6], 0.f);
}

// -------- gather2 (+ fused norm/bias): per-dst gather-sum of x2 -> out ------
__global__ void gather2_kernel(float* __restrict__ out,
                               const float* __restrict__ b2) {
    int i = blockIdx.x * blockDim.x + threadIdx.x;
    if (i >= N_NODES) return;
    int p0 = g_off[i], p1 = g_off[i + 1];

    float4 A = make_float4(0.f, 0.f, 0.f, 0.f), B = A;
    for (int p = p0; p < p1; p++) {
        int s = g_csr_src[p];
        const float4* xs =
            reinterpret_cast<const float4*>(g_x2 + (long long)s * OUTP);
        float4 t0 = __ldg(xs + 0), t1 = __ldg(xs + 1);
        A.x += t0.x; A.y += t0.y; A.z += t0.z; A.w += t0.w;
        B.x += t1.x; B.y += t1.y; B.z += t1.z;
    }
    float nd = g_norm_dst[i];
    float* o = out + (long long)i * OUTF;
    o[0] = A.x * nd + __ldg(b2 + 0);
    o[1] = A.y * nd + __ldg(b2 + 1);
    o[2] = A.z * nd + __ldg(b2 + 2);
    o[3] = A.w * nd + __ldg(b2 + 3);
    o[4] = B.x * nd + __ldg(b2 + 4);
    o[5] = B.y * nd + __ldg(b2 + 5);
    o[6] = B.z * nd + __ldg(b2 + 6);
}

// ---------------- launch -----------------------------------------------------
// gemm1 stays the 4th launch (ncu captures launch #4).
extern "C" void kernel_launch(void* const* d_in, const int* in_sizes, int n_in,
                              void* d_out, int out_size) {
    const float* feat = (const float*)d_in[0];
    const long long* ei = (const long long*)d_in[1];
    const float* W1 = (const float*)d_in[2];
    const float* b1 = (const float*)d_in[3];
    const float* W2 = (const float*)d_in[4];
    const float* b2 = (const float*)d_in[5];
    float* out = (float*)d_out;

    (void)in_sizes; (void)n_in; (void)out_size;

    zero_detect_kernel<<<(N_NODES + 255) / 256, 256>>>(
        (const unsigned long long*)ei);
    degree_kernel<<<(N_EDGES + 255) / 256, 256>>>(ei);
    scan1_kernel<<<SCAN_NBLK, SCAN_BLK>>>();   // + fused norm computation

    cudaFuncSetAttribute(gemm1_kernel,
                         cudaFuncAttributeMaxDynamicSharedMemorySize,
                         SMEM_TOTAL);
    gemm1_kernel<<<G1_GRID, G1_THREADS, SMEM_TOTAL>>>(feat, W1);

    scan2_kernel<<<1, 128>>>();
    scan3_kernel<<<(N_NODES + 255) / 256, 256>>>();
    fill_kernel<<<(N_EDGES + 255) / 256, 256>>>(ei);

    gather1_kernel<<<(N_NODES + 255) / 256, 256>>>(b1, W2);
    gather2_kernel<<<(N_NODES + 255) / 256, 256>>>(out, b2);
}